// round 2
// baseline (speedup 1.0000x reference)
#include <cuda_runtime.h>
#include <cuda_bf16.h>
#include <math.h>

#define N_NODES 50000
#define F_IN    50
#define H1      128
#define H2      64

// ---- scratch (no allocations allowed; __device__ globals per pitfalls.md) ----
__device__ __align__(16) float g_H[N_NODES * H1];   // h = x @ W_gcn
__device__ __align__(16) float g_OUT[N_NODES * H1]; // aggregated GCN output
__device__ int   g_deg[N_NODES];                    // in-degree at dst (excl. self-loop)
__device__ float g_dinv[N_NODES];                   // rsqrt(deg + 1)
__device__ float g_colsum[H1];                      // sum over nodes of relu(out + b)

// ---------------------------------------------------------------------------
// 0) zero deg + colsum
__global__ void k_zero() {
    int i = blockIdx.x * blockDim.x + threadIdx.x;
    if (i < N_NODES) g_deg[i] = 0;
    if (i < H1) g_colsum[i] = 0.0f;
}

// 1) degree count at dst  (edge_index is int32: JAX silently downcasts int64)
__global__ void k_deg(const int* __restrict__ ei, int E) {
    int i = blockIdx.x * blockDim.x + threadIdx.x;
    if (i < E) {
        int dst = ei[E + i];
        atomicAdd(&g_deg[dst], 1);
    }
}

// 2) dinv = rsqrt(deg + 1)   (self-loop guarantees deg >= 1)
__global__ void k_dinv() {
    int i = blockIdx.x * blockDim.x + threadIdx.x;
    if (i < N_NODES) {
        g_dinv[i] = rsqrtf((float)(g_deg[i] + 1));
    }
}

// 3) h = x @ W_gcn; OUT initialized with the self-loop term dinv[i]^2 * h[i]
#define NODES_PER_BLOCK 32
__global__ void k_gemm(const float* __restrict__ x, const float* __restrict__ W) {
    __shared__ float sW[F_IN * H1];              // 25.6 KB
    __shared__ float sx[NODES_PER_BLOCK * F_IN]; // 6.4 KB
    int t = threadIdx.x; // 0..127 -> output feature
    for (int i = t; i < F_IN * H1; i += 128) sW[i] = W[i];
    int node0 = blockIdx.x * NODES_PER_BLOCK;
    int nlocal = min(NODES_PER_BLOCK, N_NODES - node0);
    for (int i = t; i < nlocal * F_IN; i += 128)
        sx[i] = x[node0 * F_IN + i];
    __syncthreads();

    for (int n = 0; n < nlocal; n++) {
        float acc = 0.0f;
        const float* xr = &sx[n * F_IN];
        #pragma unroll
        for (int k = 0; k < F_IN; k++)
            acc = fmaf(xr[k], sW[k * H1 + t], acc);
        int node = node0 + n;
        g_H[node * H1 + t] = acc;
        float di = g_dinv[node];
        g_OUT[node * H1 + t] = di * di * acc;  // self-loop contribution
    }
}

// 4) edge scatter: one warp per edge, float4 per lane, vector red.global
__global__ void k_scatter(const int* __restrict__ ei, int E) {
    int gtid = blockIdx.x * blockDim.x + threadIdx.x;
    int e = gtid >> 5;
    int lane = gtid & 31;
    if (e >= E) return;
    int src = ei[e];
    int dst = ei[E + e];
    float norm = g_dinv[src] * g_dinv[dst];
    const float4* hsrc = (const float4*)(&g_H[src * H1]);
    float4 v = hsrc[lane];
    v.x *= norm; v.y *= norm; v.z *= norm; v.w *= norm;
    float* p = &g_OUT[dst * H1 + lane * 4];
    asm volatile("red.global.add.v4.f32 [%0], {%1, %2, %3, %4};"
                 :: "l"(p), "f"(v.x), "f"(v.y), "f"(v.z), "f"(v.w) : "memory");
}

// 5) column-sum of relu(OUT + b_gcn) over all nodes
__global__ void k_reduce(const float* __restrict__ b) {
    int t = threadIdx.x;     // 0..127 feature
    float bias = b[t];
    float acc = 0.0f;
    for (int n = blockIdx.x; n < N_NODES; n += gridDim.x) {
        float v = g_OUT[n * H1 + t] + bias;
        acc += fmaxf(v, 0.0f);
    }
    atomicAdd(&g_colsum[t], acc);
}

// 6) emb = tanh( mean @ W_lin + b_lin )
__global__ void k_final(const float* __restrict__ Wl, const float* __restrict__ bl,
                        float* __restrict__ out) {
    __shared__ float mean[H1];
    int t = threadIdx.x; // 0..63
    if (t < 64) {
        mean[t]      = g_colsum[t]      * (1.0f / (float)N_NODES);
        mean[t + 64] = g_colsum[t + 64] * (1.0f / (float)N_NODES);
    }
    __syncthreads();
    float acc = bl[t];
    #pragma unroll 8
    for (int k = 0; k < H1; k++)
        acc = fmaf(mean[k], Wl[k * H2 + t], acc);
    out[t] = tanhf(acc);
}

// ---------------------------------------------------------------------------
extern "C" void kernel_launch(void* const* d_in, const int* in_sizes, int n_in,
                              void* d_out, int out_size) {
    const float* x  = (const float*)d_in[0];
    const float* Wg = (const float*)d_in[1];
    const float* bg = (const float*)d_in[2];
    const float* Wl = (const float*)d_in[3];
    const float* bl = (const float*)d_in[4];
    const int*   ei = (const int*)d_in[5];
    int E = in_sizes[5] / 2;
    float* out = (float*)d_out;

    k_zero<<<(N_NODES + 255) / 256, 256>>>();
    k_deg<<<(E + 255) / 256, 256>>>(ei, E);
    k_dinv<<<(N_NODES + 255) / 256, 256>>>();
    k_gemm<<<(N_NODES + NODES_PER_BLOCK - 1) / NODES_PER_BLOCK, 128>>>(x, Wg);
    {
        long long total = (long long)E * 32;
        int blocks = (int)((total + 255) / 256);
        k_scatter<<<blocks, 256>>>(ei, E);
    }
    k_reduce<<<512, H1>>>(bg);
    k_final<<<1, H2>>>(Wl, bl, out);
}

// round 3
// speedup vs baseline: 1.3119x; 1.3119x over previous
#include <cuda_runtime.h>
#include <cuda_fp16.h>
#include <math.h>

#define N_NODES 50000
#define F_IN    50
#define H1      128
#define H2      64
#define E_MAX   1700000

// ---- scratch (__device__ globals; no allocations allowed) ----
__device__ __align__(16) __half g_Hh[N_NODES * H1];   // h = x @ W_gcn  (fp16)
__device__ int   g_deg[N_NODES];
__device__ float g_dinv[N_NODES];
__device__ int   g_rowptr[N_NODES + 1];
__device__ int   g_cursor[N_NODES];
__device__ int   g_csrc[E_MAX];                       // CSR src lists grouped by dst
__device__ float g_colsum[H1];

// ---------------------------------------------------------------------------
// 0) zero deg + colsum
__global__ void k_zero() {
    int i = blockIdx.x * blockDim.x + threadIdx.x;
    if (i < N_NODES) g_deg[i] = 0;
    if (i < H1) g_colsum[i] = 0.0f;
}

// 1) in-degree histogram at dst (edge_index is int32)
__global__ void k_deg(const int* __restrict__ ei, int E) {
    int i = blockIdx.x * blockDim.x + threadIdx.x;
    if (i < E) atomicAdd(&g_deg[ei[E + i]], 1);
}

// 2) single-block exclusive scan over deg -> rowptr (+ cursor copy)
__global__ void k_scan() {
    __shared__ int warp_sums[32];
    __shared__ int s_carry;
    int tid = threadIdx.x, lane = tid & 31, wid = tid >> 5;
    if (tid == 0) s_carry = 0;
    __syncthreads();
    for (int base = 0; base < N_NODES; base += 1024) {
        int i = base + tid;
        int v = (i < N_NODES) ? g_deg[i] : 0;
        int x = v;
        #pragma unroll
        for (int o = 1; o < 32; o <<= 1) {
            int y = __shfl_up_sync(0xffffffffu, x, o);
            if (lane >= o) x += y;
        }
        if (lane == 31) warp_sums[wid] = x;
        __syncthreads();
        if (wid == 0) {
            int w = warp_sums[lane];
            #pragma unroll
            for (int o = 1; o < 32; o <<= 1) {
                int y = __shfl_up_sync(0xffffffffu, w, o);
                if (lane >= o) w += y;
            }
            warp_sums[lane] = w;
        }
        __syncthreads();
        int warp_off = (wid > 0) ? warp_sums[wid - 1] : 0;
        int excl = x + warp_off - v;
        int carry = s_carry;
        if (i < N_NODES) {
            g_rowptr[i] = carry + excl;
            g_cursor[i] = carry + excl;
        }
        int total = warp_sums[31];
        __syncthreads();
        if (tid == 0) s_carry = carry + total;
        __syncthreads();
    }
    if (threadIdx.x == 0) g_rowptr[N_NODES] = s_carry;
}

// 3) dinv = rsqrt(indeg + 1)  (self-loop)
__global__ void k_dinv() {
    int i = blockIdx.x * blockDim.x + threadIdx.x;
    if (i < N_NODES) g_dinv[i] = rsqrtf((float)(g_deg[i] + 1));
}

// 4) fill CSR: group srcs by dst (order within a dst irrelevant)
__global__ void k_fill(const int* __restrict__ ei, int E) {
    int i = blockIdx.x * blockDim.x + threadIdx.x;
    if (i < E) {
        int src = ei[i];
        int dst = ei[E + i];
        int pos = atomicAdd(&g_cursor[dst], 1);
        g_csrc[pos] = src;
    }
}

// 5) h = x @ W_gcn, fp16 output. 64 threads (2 features each), 4-node register block.
#define GN 32
__global__ void k_gemm(const float* __restrict__ x, const float* __restrict__ W) {
    __shared__ float sW[F_IN * H1];   // 25.6 KB
    __shared__ float sx[GN * F_IN];   // 6.4 KB
    int t = threadIdx.x;              // 0..63 -> feature pair (2t, 2t+1)
    for (int i = t; i < F_IN * H1; i += 64) sW[i] = W[i];
    int node0 = blockIdx.x * GN;
    int nl = min(GN, N_NODES - node0);   // always a multiple of 4 (50000 = 1562*32 + 16)
    for (int i = t; i < nl * F_IN; i += 64) sx[i] = x[node0 * F_IN + i];
    __syncthreads();

    int c = 2 * t;
    __half2* Hh2 = (__half2*)g_Hh;
    for (int n = 0; n < nl; n += 4) {
        float2 a0 = {0.f, 0.f}, a1 = {0.f, 0.f}, a2 = {0.f, 0.f}, a3 = {0.f, 0.f};
        #pragma unroll
        for (int k = 0; k < F_IN; k++) {
            float w0 = sW[k * H1 + c], w1 = sW[k * H1 + c + 1];
            float x0 = sx[(n + 0) * F_IN + k];
            float x1 = sx[(n + 1) * F_IN + k];
            float x2 = sx[(n + 2) * F_IN + k];
            float x3 = sx[(n + 3) * F_IN + k];
            a0.x = fmaf(x0, w0, a0.x); a0.y = fmaf(x0, w1, a0.y);
            a1.x = fmaf(x1, w0, a1.x); a1.y = fmaf(x1, w1, a1.y);
            a2.x = fmaf(x2, w0, a2.x); a2.y = fmaf(x2, w1, a2.y);
            a3.x = fmaf(x3, w0, a3.x); a3.y = fmaf(x3, w1, a3.y);
        }
        int v = node0 + n;
        Hh2[(v + 0) * 64 + t] = __float22half2_rn(a0);
        Hh2[(v + 1) * 64 + t] = __float22half2_rn(a1);
        Hh2[(v + 2) * 64 + t] = __float22half2_rn(a2);
        Hh2[(v + 3) * 64 + t] = __float22half2_rn(a3);
    }
}

// 6) dst-centric aggregate + bias + relu + colsum (OUT never materialized).
//    64 threads/block, thread t owns features (2t, 2t+1). AGG_NODES nodes/block.
#define AGG_NODES 16
__global__ void k_agg(const float* __restrict__ b) {
    int t = threadIdx.x;  // 0..63
    int node0 = blockIdx.x * AGG_NODES;
    const __half2* Hh2 = (const __half2*)g_Hh;
    float bx = b[2 * t], by = b[2 * t + 1];
    float sx = 0.f, sy = 0.f;

    int nend = min(AGG_NODES, N_NODES - node0);
    for (int n = 0; n < nend; n++) {
        int v = node0 + n;
        float dv = g_dinv[v];
        // self-loop: dinv^2 * h[v]
        float2 hv = __half22float2(Hh2[v * 64 + t]);
        float s = dv * dv;
        float ax = s * hv.x, ay = s * hv.y;

        int e = g_rowptr[v], end = g_rowptr[v + 1];
        for (; e + 1 < end; e += 2) {
            int s0 = g_csrc[e], s1 = g_csrc[e + 1];
            float n0 = dv * g_dinv[s0];
            float n1 = dv * g_dinv[s1];
            float2 m0 = __half22float2(Hh2[s0 * 64 + t]);
            float2 m1 = __half22float2(Hh2[s1 * 64 + t]);
            ax = fmaf(n0, m0.x, ax); ay = fmaf(n0, m0.y, ay);
            ax = fmaf(n1, m1.x, ax); ay = fmaf(n1, m1.y, ay);
        }
        if (e < end) {
            int s0 = g_csrc[e];
            float n0 = dv * g_dinv[s0];
            float2 m0 = __half22float2(Hh2[s0 * 64 + t]);
            ax = fmaf(n0, m0.x, ax); ay = fmaf(n0, m0.y, ay);
        }
        sx += fmaxf(ax + bx, 0.f);
        sy += fmaxf(ay + by, 0.f);
    }
    atomicAdd(&g_colsum[2 * t], sx);
    atomicAdd(&g_colsum[2 * t + 1], sy);
}

// 7) emb = tanh( mean @ W_lin + b_lin )
__global__ void k_final(const float* __restrict__ Wl, const float* __restrict__ bl,
                        float* __restrict__ out) {
    __shared__ float mean[H1];
    int t = threadIdx.x; // 0..63
    mean[t]      = g_colsum[t]      * (1.0f / (float)N_NODES);
    mean[t + 64] = g_colsum[t + 64] * (1.0f / (float)N_NODES);
    __syncthreads();
    float acc = bl[t];
    #pragma unroll 8
    for (int k = 0; k < H1; k++)
        acc = fmaf(mean[k], Wl[k * H2 + t], acc);
    out[t] = tanhf(acc);
}

// ---------------------------------------------------------------------------
extern "C" void kernel_launch(void* const* d_in, const int* in_sizes, int n_in,
                              void* d_out, int out_size) {
    const float* x  = (const float*)d_in[0];
    const float* Wg = (const float*)d_in[1];
    const float* bg = (const float*)d_in[2];
    const float* Wl = (const float*)d_in[3];
    const float* bl = (const float*)d_in[4];
    const int*   ei = (const int*)d_in[5];
    int E = in_sizes[5] / 2;
    float* out = (float*)d_out;

    k_zero<<<(N_NODES + 255) / 256, 256>>>();
    k_deg<<<(E + 255) / 256, 256>>>(ei, E);
    k_scan<<<1, 1024>>>();
    k_dinv<<<(N_NODES + 255) / 256, 256>>>();
    k_fill<<<(E + 255) / 256, 256>>>(ei, E);
    k_gemm<<<(N_NODES + GN - 1) / GN, 64>>>(x, Wg);
    k_agg<<<(N_NODES + AGG_NODES - 1) / AGG_NODES, 64>>>(bg);
    k_final<<<1, H2>>>(Wl, bl, out);
}